// round 2
// baseline (speedup 1.0000x reference)
#include <cuda_runtime.h>
#include <cstdint>

#define HDIM 64
#define BN_EPS 1e-5f
#define MAXN 131072

// Scratch (device globals — no allocation allowed). 16B-aligned for float4.
__device__ __align__(16) float g_y[MAXN * HDIM];    // y = h @ Wa
__device__ __align__(16) float g_z[MAXN * HDIM];    // z = (1+eps)*y + scatter(y)
__device__ __align__(16) float g_h2[MAXN * HDIM];   // pre-BN output of MLP
__device__ __align__(16) float g_h[MAXN * HDIM];    // layer input / residual
__device__ __align__(16) float g_sum[HDIM];
__device__ __align__(16) float g_sumsq[HDIM];
__device__ __align__(16) float g_scale[HDIM];
__device__ __align__(16) float g_shift[HDIM];

// ---------------------------------------------------------------------------
// GEMM A: y = A @ W  (A: N x K, W: K x 64). Epilogue writes y and z=(1+eps)*y.
// Block tile 128x64, 256 threads, per-thread 8x4. W fully staged in smem.
// Block 0 also zeroes the BN-stat accumulators for this layer.
// ---------------------------------------------------------------------------
template <int K>
__global__ __launch_bounds__(256) void gemm_a_kernel(
    const float* __restrict__ A, const float* __restrict__ W,
    const float* __restrict__ eps_ptr, int eps_idx,
    float* __restrict__ y, float* __restrict__ z, int N)
{
    constexpr int BM = 128, BK = 16;
    __shared__ float Ws[K][HDIM];        // K*64*4 B
    __shared__ float AsT[BK][BM + 1];    // transposed A tile, padded

    const int tid = threadIdx.x;
    const int tx = tid & 15;             // output col group (4 cols)
    const int ty = tid >> 4;             // output row group (8 rows)
    const int r0 = blockIdx.x * BM;

    if (blockIdx.x == 0 && tid < HDIM) { g_sum[tid] = 0.f; g_sumsq[tid] = 0.f; }

    // Load W into shared (contiguous)
    {
        const float4* W4 = (const float4*)W;
        float4* Ws4 = (float4*)&Ws[0][0];
        #pragma unroll
        for (int i = tid; i < K * HDIM / 4; i += 256) Ws4[i] = W4[i];
    }

    float acc[8][4];
    #pragma unroll
    for (int i = 0; i < 8; i++)
        #pragma unroll
        for (int j = 0; j < 4; j++) acc[i][j] = 0.f;

    for (int kk = 0; kk < K; kk += BK) {
        __syncthreads();
        // Load A tile rows r0..r0+127, cols kk..kk+15, store transposed
        #pragma unroll
        for (int p = 0; p < 2; p++) {
            int row = (tid >> 2) + p * 64;
            int c4 = (tid & 3) * 4;
            int gr = r0 + row;
            float4 v = make_float4(0.f, 0.f, 0.f, 0.f);
            if (gr < N) v = *(const float4*)(A + (size_t)gr * K + kk + c4);
            AsT[c4 + 0][row] = v.x;
            AsT[c4 + 1][row] = v.y;
            AsT[c4 + 2][row] = v.z;
            AsT[c4 + 3][row] = v.w;
        }
        __syncthreads();
        #pragma unroll
        for (int k = 0; k < BK; k++) {
            float4 bv = *(const float4*)&Ws[kk + k][tx * 4];
            float a[8];
            #pragma unroll
            for (int i = 0; i < 8; i++) a[i] = AsT[k][ty * 8 + i];
            #pragma unroll
            for (int i = 0; i < 8; i++) {
                acc[i][0] = fmaf(a[i], bv.x, acc[i][0]);
                acc[i][1] = fmaf(a[i], bv.y, acc[i][1]);
                acc[i][2] = fmaf(a[i], bv.z, acc[i][2]);
                acc[i][3] = fmaf(a[i], bv.w, acc[i][3]);
            }
        }
    }

    const float ep = 1.0f + eps_ptr[eps_idx];
    #pragma unroll
    for (int i = 0; i < 8; i++) {
        int gr = r0 + ty * 8 + i;
        if (gr < N) {
            float4 o = make_float4(acc[i][0], acc[i][1], acc[i][2], acc[i][3]);
            ((float4*)y)[(size_t)gr * 16 + tx] = o;
            float4 zo = make_float4(o.x * ep, o.y * ep, o.z * ep, o.w * ep);
            ((float4*)z)[(size_t)gr * 16 + tx] = zo;
        }
    }
}

// ---------------------------------------------------------------------------
// Scatter: z[dst] += w * y[src], 64-dim, vector atomics. 64 edges per block.
// Indices are int32 (JAX demotes int64 with x64 disabled).
// ---------------------------------------------------------------------------
__global__ __launch_bounds__(256) void scatter_kernel(
    const int* __restrict__ src, const int* __restrict__ dst,
    const float* __restrict__ ew, const float* __restrict__ y,
    float* __restrict__ z, int E)
{
    __shared__ int s_src[64], s_dst[64];
    __shared__ float s_w[64];
    const int base = blockIdx.x * 64;
    const int tid = threadIdx.x;
    if (tid < 64) {
        int e = base + tid;
        if (e < E) {
            s_src[tid] = src[e];
            s_dst[tid] = dst[e];
            s_w[tid] = ew[e];
        }
    }
    __syncthreads();
    #pragma unroll
    for (int it = 0; it < 4; it++) {
        int idx = it * 256 + tid;
        int e = idx >> 4;
        int c = idx & 15;
        if (base + e < E) {
            float w = s_w[e];
            float4 v = ((const float4*)y)[(size_t)s_src[e] * 16 + c];
            float4 r = make_float4(v.x * w, v.y * w, v.z * w, v.w * w);
            float4* p = (float4*)z + (size_t)s_dst[e] * 16 + c;
            asm volatile("red.global.add.v4.f32 [%0], {%1,%2,%3,%4};"
                         :: "l"(p), "f"(r.x), "f"(r.y), "f"(r.z), "f"(r.w)
                         : "memory");
        }
    }
}

// ---------------------------------------------------------------------------
// GEMM B: h2 = relu(z + ba) @ W + bb, with BN-stat accumulation (K=64 fixed).
// ---------------------------------------------------------------------------
__global__ __launch_bounds__(256) void gemm_b_kernel(
    const float* __restrict__ Zin, const float* __restrict__ W,
    const float* __restrict__ ba, const float* __restrict__ bb,
    float* __restrict__ h2, int N)
{
    constexpr int K = HDIM, BM = 128, BK = 16;
    __shared__ float Ws[K][HDIM];
    __shared__ float AsT[BK][BM + 1];
    __shared__ float s_sum[HDIM], s_ssq[HDIM];

    const int tid = threadIdx.x;
    const int tx = tid & 15;
    const int ty = tid >> 4;
    const int r0 = blockIdx.x * BM;

    if (tid < HDIM) { s_sum[tid] = 0.f; s_ssq[tid] = 0.f; }

    {
        const float4* W4 = (const float4*)W;
        float4* Ws4 = (float4*)&Ws[0][0];
        #pragma unroll
        for (int i = tid; i < K * HDIM / 4; i += 256) Ws4[i] = W4[i];
    }

    float acc[8][4];
    #pragma unroll
    for (int i = 0; i < 8; i++)
        #pragma unroll
        for (int j = 0; j < 4; j++) acc[i][j] = 0.f;

    for (int kk = 0; kk < K; kk += BK) {
        __syncthreads();
        #pragma unroll
        for (int p = 0; p < 2; p++) {
            int row = (tid >> 2) + p * 64;
            int c4 = (tid & 3) * 4;
            int gr = r0 + row;
            float4 v = make_float4(0.f, 0.f, 0.f, 0.f);
            if (gr < N) {
                v = *(const float4*)(Zin + (size_t)gr * K + kk + c4);
                float4 b = *(const float4*)(ba + kk + c4);
                v.x = fmaxf(v.x + b.x, 0.f);
                v.y = fmaxf(v.y + b.y, 0.f);
                v.z = fmaxf(v.z + b.z, 0.f);
                v.w = fmaxf(v.w + b.w, 0.f);
            }
            AsT[c4 + 0][row] = v.x;
            AsT[c4 + 1][row] = v.y;
            AsT[c4 + 2][row] = v.z;
            AsT[c4 + 3][row] = v.w;
        }
        __syncthreads();
        #pragma unroll
        for (int k = 0; k < BK; k++) {
            float4 bv = *(const float4*)&Ws[kk + k][tx * 4];
            float a[8];
            #pragma unroll
            for (int i = 0; i < 8; i++) a[i] = AsT[k][ty * 8 + i];
            #pragma unroll
            for (int i = 0; i < 8; i++) {
                acc[i][0] = fmaf(a[i], bv.x, acc[i][0]);
                acc[i][1] = fmaf(a[i], bv.y, acc[i][1]);
                acc[i][2] = fmaf(a[i], bv.z, acc[i][2]);
                acc[i][3] = fmaf(a[i], bv.w, acc[i][3]);
            }
        }
    }

    const float4 bb4 = *(const float4*)(bb + tx * 4);
    float csum[4] = {0.f, 0.f, 0.f, 0.f};
    float cssq[4] = {0.f, 0.f, 0.f, 0.f};
    #pragma unroll
    for (int i = 0; i < 8; i++) {
        int gr = r0 + ty * 8 + i;
        if (gr < N) {
            float4 o = make_float4(acc[i][0] + bb4.x, acc[i][1] + bb4.y,
                                   acc[i][2] + bb4.z, acc[i][3] + bb4.w);
            ((float4*)h2)[(size_t)gr * 16 + tx] = o;
            csum[0] += o.x; cssq[0] += o.x * o.x;
            csum[1] += o.y; cssq[1] += o.y * o.y;
            csum[2] += o.z; cssq[2] += o.z * o.z;
            csum[3] += o.w; cssq[3] += o.w * o.w;
        }
    }
    __syncthreads();   // s_sum init visible (also separates from AsT use)
    #pragma unroll
    for (int j = 0; j < 4; j++) {
        atomicAdd(&s_sum[tx * 4 + j], csum[j]);
        atomicAdd(&s_ssq[tx * 4 + j], cssq[j]);
    }
    __syncthreads();
    if (tid < HDIM) {
        atomicAdd(&g_sum[tid], s_sum[tid]);
        atomicAdd(&g_sumsq[tid], s_ssq[tid]);
    }
}

// ---------------------------------------------------------------------------
// BN finalize: scale/shift from accumulated stats. 1 block, 64 threads.
// ---------------------------------------------------------------------------
__global__ void bn_finalize_kernel(const float* __restrict__ gamma,
                                   const float* __restrict__ beta, float invN)
{
    int j = threadIdx.x;
    float mean = g_sum[j] * invN;
    float var = g_sumsq[j] * invN - mean * mean;
    float sc = gamma[j] * rsqrtf(var + BN_EPS);
    g_scale[j] = sc;
    g_shift[j] = beta[j] - mean * sc;
}

// ---------------------------------------------------------------------------
// BN apply (+ReLU, + optional residual): out = [hprev +] relu(h2*scale+shift)
// ---------------------------------------------------------------------------
__global__ __launch_bounds__(256) void bn_apply_kernel(
    const float* __restrict__ h2, const float* __restrict__ hprev,
    float* __restrict__ out, int N, int residual)
{
    int idx = blockIdx.x * 256 + threadIdx.x;   // one float4 each
    if (idx >= N * 16) return;
    int c4 = (idx & 15) * 4;
    float4 v = ((const float4*)h2)[idx];
    float4 sc = *(const float4*)&g_scale[c4];
    float4 sh = *(const float4*)&g_shift[c4];
    v.x = fmaxf(fmaf(v.x, sc.x, sh.x), 0.f);
    v.y = fmaxf(fmaf(v.y, sc.y, sh.y), 0.f);
    v.z = fmaxf(fmaf(v.z, sc.z, sh.z), 0.f);
    v.w = fmaxf(fmaf(v.w, sc.w, sh.w), 0.f);
    if (residual) {
        float4 p = ((const float4*)hprev)[idx];
        v.x += p.x; v.y += p.y; v.z += p.z; v.w += p.w;
    }
    ((float4*)out)[idx] = v;
}

// ---------------------------------------------------------------------------
// Host launcher
// ---------------------------------------------------------------------------
extern "C" void kernel_launch(void* const* d_in, const int* in_sizes, int n_in,
                              void* d_out, int out_size)
{
    const float* x        = (const float*)d_in[0];
    const int* ei         = (const int*)d_in[1];   // int32 (JAX x64 disabled)
    const float* ew       = (const float*)d_in[2];
    const float* eps1     = (const float*)d_in[3];
    const float* W1a      = (const float*)d_in[4];
    const float* b1a      = (const float*)d_in[5];
    const float* W1b      = (const float*)d_in[6];
    const float* b1b      = (const float*)d_in[7];
    const float* g1       = (const float*)d_in[8];
    const float* be1      = (const float*)d_in[9];
    const float* epss     = (const float*)d_in[10];
    const float* Wsa      = (const float*)d_in[11];
    const float* bsa      = (const float*)d_in[12];
    const float* Wsb      = (const float*)d_in[13];
    const float* bsb      = (const float*)d_in[14];
    const float* gs       = (const float*)d_in[15];
    const float* bes      = (const float*)d_in[16];

    const int F  = in_sizes[4] / in_sizes[5];   // 128
    const int N  = in_sizes[0] / F;
    const int E  = in_sizes[2];
    const int Lm1 = in_sizes[10];

    const int* src = ei;
    const int* dst = ei + E;

    float *yb, *zb, *h2b, *hb;
    cudaGetSymbolAddress((void**)&yb,  g_y);
    cudaGetSymbolAddress((void**)&zb,  g_z);
    cudaGetSymbolAddress((void**)&h2b, g_h2);
    cudaGetSymbolAddress((void**)&hb,  g_h);

    const int gemm_blocks = (N + 127) / 128;
    const int scat_blocks = (E + 63) / 64;
    const int bn_blocks   = (N * 16 + 255) / 256;
    const float invN = 1.0f / (float)N;

    // -------- Layer 1 (K = F = 128) --------
    gemm_a_kernel<128><<<gemm_blocks, 256>>>(x, W1a, eps1, 0, yb, zb, N);
    scatter_kernel<<<scat_blocks, 256>>>(src, dst, ew, yb, zb, E);
    gemm_b_kernel<<<gemm_blocks, 256>>>(zb, W1b, b1a, b1b, h2b, N);
    bn_finalize_kernel<<<1, HDIM>>>(g1, be1, invN);
    bn_apply_kernel<<<bn_blocks, 256>>>(h2b, yb /*unused*/, hb, N, 0);

    // -------- Layers 2..L (K = 64, residual) --------
    for (int l = 0; l < Lm1; l++) {
        gemm_a_kernel<64><<<gemm_blocks, 256>>>(hb, Wsa + (size_t)l * HDIM * HDIM,
                                                epss, l, yb, zb, N);
        scatter_kernel<<<scat_blocks, 256>>>(src, dst, ew, yb, zb, E);
        gemm_b_kernel<<<gemm_blocks, 256>>>(zb, Wsb + (size_t)l * HDIM * HDIM,
                                            bsa + (size_t)l * HDIM,
                                            bsb + (size_t)l * HDIM, h2b, N);
        bn_finalize_kernel<<<1, HDIM>>>(gs + (size_t)l * HDIM,
                                        bes + (size_t)l * HDIM, invN);
        float* outp = (l == Lm1 - 1) ? (float*)d_out : hb;
        bn_apply_kernel<<<bn_blocks, 256>>>(h2b, hb, outp, N, 1);
    }
}

// round 3
// speedup vs baseline: 1.0383x; 1.0383x over previous
#include <cuda_runtime.h>
#include <cstdint>

#define HDIM 64
#define BN_EPS 1e-5f
#define MAXN 131072
#define MAXL 4

// Scratch (device globals — no allocation allowed). 16B-aligned for float4.
__device__ __align__(16) float g_y[MAXN * HDIM];    // y = h @ Wa
__device__ __align__(16) float g_z[MAXN * HDIM];    // z = (1+eps)*y + scatter
__device__ __align__(16) float g_h2[MAXN * HDIM];   // pre-BN output of MLP
__device__ __align__(16) float g_h[MAXN * HDIM];    // residual stream
__device__ __align__(16) float g_sum[MAXL][HDIM];   // per-layer BN stats
__device__ __align__(16) float g_sumsq[MAXL][HDIM];

// Packed fp32x2 helpers (Blackwell FFMA2 path — 2x fp32 FMA throughput)
#define PACK2(out, lo, hi) \
    asm("mov.b64 %0, {%1, %2};" : "=l"(out) : "f"(lo), "f"(hi))
#define UNPACK2(lo, hi, in) \
    asm("mov.b64 {%0, %1}, %2;" : "=f"(lo), "=f"(hi) : "l"(in))
#define FMA2(acc, a, b) \
    asm("fma.rn.f32x2 %0, %1, %2, %0;" : "+l"(acc) : "l"(a), "l"(b))

// ---------------------------------------------------------------------------
// GEMM A: y = A' @ W, where A' is either x (layer 0) or the fused
// residual+BN+ReLU of the previous layer's h2 (FUSE=true), which is also
// written back to hbuf as the new residual stream.
// Epilogue writes y and z = (1+eps)*y. Block 128x64, 256 thr, 8x4/thread,
// accumulators packed f32x2 over row pairs.
// ---------------------------------------------------------------------------
template <int K, bool FUSE>
__global__ __launch_bounds__(256) void gemm_a_kernel(
    const float* __restrict__ A, const float* __restrict__ W,
    const float* __restrict__ eps_ptr, int eps_idx,
    const float* __restrict__ gamma, const float* __restrict__ beta,
    int stat_set, int residual, float invN, int zero_stats,
    float* __restrict__ hbuf,
    float* __restrict__ y, float* __restrict__ z, int N)
{
    constexpr int BM = 128, BK = 16;
    __shared__ __align__(16) float Ws[K][HDIM];
    __shared__ __align__(16) float AsT[BK][BM + 2];   // +2 keeps rows 8B-aligned
    __shared__ __align__(16) float s_scale[HDIM], s_shift[HDIM];

    const int tid = threadIdx.x;
    const int tx = tid & 15;             // output col group (4 cols)
    const int ty = tid >> 4;             // output row group (8 rows)
    const int r0 = blockIdx.x * BM;

    if (FUSE && tid < HDIM) {
        float mean = g_sum[stat_set][tid] * invN;
        float var  = g_sumsq[stat_set][tid] * invN - mean * mean;
        float sc   = gamma[tid] * rsqrtf(var + BN_EPS);
        s_scale[tid] = sc;
        s_shift[tid] = beta[tid] - mean * sc;
    }
    if (zero_stats && blockIdx.x == 0 && tid < HDIM) {
        #pragma unroll
        for (int s = 0; s < MAXL; s++) { g_sum[s][tid] = 0.f; g_sumsq[s][tid] = 0.f; }
    }

    {   // stage W
        const float4* W4 = (const float4*)W;
        float4* Ws4 = (float4*)&Ws[0][0];
        #pragma unroll
        for (int i = tid; i < K * HDIM / 4; i += 256) Ws4[i] = W4[i];
    }

    unsigned long long accp[4][4];       // [row-pair][col], each = 2 rows packed
    #pragma unroll
    for (int p = 0; p < 4; p++)
        #pragma unroll
        for (int j = 0; j < 4; j++) accp[p][j] = 0ull;

    for (int kk = 0; kk < K; kk += BK) {
        __syncthreads();                 // covers s_scale init before first use
        #pragma unroll
        for (int pp = 0; pp < 2; pp++) {
            int row = (tid >> 2) + pp * 64;
            int c4 = (tid & 3) * 4;
            int gr = r0 + row;
            float4 v = make_float4(0.f, 0.f, 0.f, 0.f);
            if (gr < N) {
                v = *(const float4*)(A + (size_t)gr * K + kk + c4);
                if (FUSE) {
                    float4 sc = *(const float4*)&s_scale[kk + c4];
                    float4 sh = *(const float4*)&s_shift[kk + c4];
                    v.x = fmaxf(fmaf(v.x, sc.x, sh.x), 0.f);
                    v.y = fmaxf(fmaf(v.y, sc.y, sh.y), 0.f);
                    v.z = fmaxf(fmaf(v.z, sc.z, sh.z), 0.f);
                    v.w = fmaxf(fmaf(v.w, sc.w, sh.w), 0.f);
                    float* hp = hbuf + (size_t)gr * K + kk + c4;
                    if (residual) {
                        float4 h = *(const float4*)hp;
                        v.x += h.x; v.y += h.y; v.z += h.z; v.w += h.w;
                    }
                    *(float4*)hp = v;    // new residual stream
                }
            }
            AsT[(tid & 3) * 4 + 0][row] = v.x;
            AsT[(tid & 3) * 4 + 1][row] = v.y;
            AsT[(tid & 3) * 4 + 2][row] = v.z;
            AsT[(tid & 3) * 4 + 3][row] = v.w;
        }
        __syncthreads();
        #pragma unroll
        for (int k = 0; k < BK; k++) {
            float4 bv = *(const float4*)&Ws[kk + k][tx * 4];
            unsigned long long b0, b1, b2, b3;
            PACK2(b0, bv.x, bv.x); PACK2(b1, bv.y, bv.y);
            PACK2(b2, bv.z, bv.z); PACK2(b3, bv.w, bv.w);
            #pragma unroll
            for (int p = 0; p < 4; p++) {
                unsigned long long ap =
                    *(const unsigned long long*)&AsT[k][ty * 8 + 2 * p];
                FMA2(accp[p][0], ap, b0);
                FMA2(accp[p][1], ap, b1);
                FMA2(accp[p][2], ap, b2);
                FMA2(accp[p][3], ap, b3);
            }
        }
    }

    const float ep = 1.0f + eps_ptr[eps_idx];
    #pragma unroll
    for (int p = 0; p < 4; p++) {
        float lo0, hi0, lo1, hi1, lo2, hi2, lo3, hi3;
        UNPACK2(lo0, hi0, accp[p][0]);
        UNPACK2(lo1, hi1, accp[p][1]);
        UNPACK2(lo2, hi2, accp[p][2]);
        UNPACK2(lo3, hi3, accp[p][3]);
        int gr = r0 + ty * 8 + 2 * p;
        if (gr < N) {
            float4 o = make_float4(lo0, lo1, lo2, lo3);
            ((float4*)y)[(size_t)gr * 16 + tx] = o;
            ((float4*)z)[(size_t)gr * 16 + tx] =
                make_float4(o.x * ep, o.y * ep, o.z * ep, o.w * ep);
        }
        if (gr + 1 < N) {
            float4 o = make_float4(hi0, hi1, hi2, hi3);
            ((float4*)y)[(size_t)(gr + 1) * 16 + tx] = o;
            ((float4*)z)[(size_t)(gr + 1) * 16 + tx] =
                make_float4(o.x * ep, o.y * ep, o.z * ep, o.w * ep);
        }
    }
}

// ---------------------------------------------------------------------------
// Scatter: z[dst] += w * y[src], 64-dim, vector red atomics. int32 indices.
// ---------------------------------------------------------------------------
__global__ __launch_bounds__(256) void scatter_kernel(
    const int* __restrict__ src, const int* __restrict__ dst,
    const float* __restrict__ ew, const float* __restrict__ y,
    float* __restrict__ z, int E)
{
    __shared__ int s_src[64], s_dst[64];
    __shared__ float s_w[64];
    const int base = blockIdx.x * 64;
    const int tid = threadIdx.x;
    if (tid < 64) {
        int e = base + tid;
        if (e < E) { s_src[tid] = src[e]; s_dst[tid] = dst[e]; s_w[tid] = ew[e]; }
    }
    __syncthreads();
    #pragma unroll
    for (int it = 0; it < 4; it++) {
        int idx = it * 256 + tid;
        int e = idx >> 4;
        int c = idx & 15;
        if (base + e < E) {
            float w = s_w[e];
            float4 v = ((const float4*)y)[(size_t)s_src[e] * 16 + c];
            float4 r = make_float4(v.x * w, v.y * w, v.z * w, v.w * w);
            float4* p = (float4*)z + (size_t)s_dst[e] * 16 + c;
            asm volatile("red.global.add.v4.f32 [%0], {%1,%2,%3,%4};"
                         :: "l"(p), "f"(r.x), "f"(r.y), "f"(r.z), "f"(r.w)
                         : "memory");
        }
    }
}

// ---------------------------------------------------------------------------
// GEMM B: h2 = relu(z + ba) @ W + bb, BN stats accumulated into set stat_set.
// ---------------------------------------------------------------------------
__global__ __launch_bounds__(256) void gemm_b_kernel(
    const float* __restrict__ Zin, const float* __restrict__ W,
    const float* __restrict__ ba, const float* __restrict__ bb,
    float* __restrict__ h2, int N, int stat_set)
{
    constexpr int K = HDIM, BM = 128, BK = 16;
    __shared__ __align__(16) float Ws[K][HDIM];
    __shared__ __align__(16) float AsT[BK][BM + 2];
    __shared__ float s_sum[HDIM], s_ssq[HDIM];

    const int tid = threadIdx.x;
    const int tx = tid & 15;
    const int ty = tid >> 4;
    const int r0 = blockIdx.x * BM;

    if (tid < HDIM) { s_sum[tid] = 0.f; s_ssq[tid] = 0.f; }

    {
        const float4* W4 = (const float4*)W;
        float4* Ws4 = (float4*)&Ws[0][0];
        #pragma unroll
        for (int i = tid; i < K * HDIM / 4; i += 256) Ws4[i] = W4[i];
    }

    unsigned long long accp[4][4];
    #pragma unroll
    for (int p = 0; p < 4; p++)
        #pragma unroll
        for (int j = 0; j < 4; j++) accp[p][j] = 0ull;

    for (int kk = 0; kk < K; kk += BK) {
        __syncthreads();
        #pragma unroll
        for (int pp = 0; pp < 2; pp++) {
            int row = (tid >> 2) + pp * 64;
            int c4 = (tid & 3) * 4;
            int gr = r0 + row;
            float4 v = make_float4(0.f, 0.f, 0.f, 0.f);
            if (gr < N) {
                v = *(const float4*)(Zin + (size_t)gr * K + kk + c4);
                float4 b = *(const float4*)(ba + kk + c4);
                v.x = fmaxf(v.x + b.x, 0.f);
                v.y = fmaxf(v.y + b.y, 0.f);
                v.z = fmaxf(v.z + b.z, 0.f);
                v.w = fmaxf(v.w + b.w, 0.f);
            }
            AsT[c4 + 0][row] = v.x;
            AsT[c4 + 1][row] = v.y;
            AsT[c4 + 2][row] = v.z;
            AsT[c4 + 3][row] = v.w;
        }
        __syncthreads();
        #pragma unroll
        for (int k = 0; k < BK; k++) {
            float4 bv = *(const float4*)&Ws[kk + k][tx * 4];
            unsigned long long b0, b1, b2, b3;
            PACK2(b0, bv.x, bv.x); PACK2(b1, bv.y, bv.y);
            PACK2(b2, bv.z, bv.z); PACK2(b3, bv.w, bv.w);
            #pragma unroll
            for (int p = 0; p < 4; p++) {
                unsigned long long ap =
                    *(const unsigned long long*)&AsT[k][ty * 8 + 2 * p];
                FMA2(accp[p][0], ap, b0);
                FMA2(accp[p][1], ap, b1);
                FMA2(accp[p][2], ap, b2);
                FMA2(accp[p][3], ap, b3);
            }
        }
    }

    const float4 bb4 = *(const float4*)(bb + tx * 4);
    float csum[4] = {0.f, 0.f, 0.f, 0.f};
    float cssq[4] = {0.f, 0.f, 0.f, 0.f};
    #pragma unroll
    for (int p = 0; p < 4; p++) {
        float lo0, hi0, lo1, hi1, lo2, hi2, lo3, hi3;
        UNPACK2(lo0, hi0, accp[p][0]);
        UNPACK2(lo1, hi1, accp[p][1]);
        UNPACK2(lo2, hi2, accp[p][2]);
        UNPACK2(lo3, hi3, accp[p][3]);
        int gr = r0 + ty * 8 + 2 * p;
        if (gr < N) {
            float4 o = make_float4(lo0 + bb4.x, lo1 + bb4.y, lo2 + bb4.z, lo3 + bb4.w);
            ((float4*)h2)[(size_t)gr * 16 + tx] = o;
            csum[0] += o.x; cssq[0] += o.x * o.x;
            csum[1] += o.y; cssq[1] += o.y * o.y;
            csum[2] += o.z; cssq[2] += o.z * o.z;
            csum[3] += o.w; cssq[3] += o.w * o.w;
        }
        if (gr + 1 < N) {
            float4 o = make_float4(hi0 + bb4.x, hi1 + bb4.y, hi2 + bb4.z, hi3 + bb4.w);
            ((float4*)h2)[(size_t)(gr + 1) * 16 + tx] = o;
            csum[0] += o.x; cssq[0] += o.x * o.x;
            csum[1] += o.y; cssq[1] += o.y * o.y;
            csum[2] += o.z; cssq[2] += o.z * o.z;
            csum[3] += o.w; cssq[3] += o.w * o.w;
        }
    }
    __syncthreads();
    #pragma unroll
    for (int j = 0; j < 4; j++) {
        atomicAdd(&s_sum[tx * 4 + j], csum[j]);
        atomicAdd(&s_ssq[tx * 4 + j], cssq[j]);
    }
    __syncthreads();
    if (tid < HDIM) {
        atomicAdd(&g_sum[stat_set][tid], s_sum[tid]);
        atomicAdd(&g_sumsq[stat_set][tid], s_ssq[tid]);
    }
}

// ---------------------------------------------------------------------------
// Final BN apply + residual into d_out (scale/shift recomputed per block).
// ---------------------------------------------------------------------------
__global__ __launch_bounds__(256) void bn_apply_final_kernel(
    const float* __restrict__ h2, const float* __restrict__ hprev,
    float* __restrict__ out,
    const float* __restrict__ gamma, const float* __restrict__ beta,
    int stat_set, float invN, int N)
{
    __shared__ __align__(16) float s_scale[HDIM], s_shift[HDIM];
    const int tid = threadIdx.x;
    if (tid < HDIM) {
        float mean = g_sum[stat_set][tid] * invN;
        float var  = g_sumsq[stat_set][tid] * invN - mean * mean;
        float sc   = gamma[tid] * rsqrtf(var + BN_EPS);
        s_scale[tid] = sc;
        s_shift[tid] = beta[tid] - mean * sc;
    }
    __syncthreads();
    int idx = blockIdx.x * 256 + tid;
    if (idx >= N * 16) return;
    int c4 = (idx & 15) * 4;
    float4 v = ((const float4*)h2)[idx];
    float4 sc = *(const float4*)&s_scale[c4];
    float4 sh = *(const float4*)&s_shift[c4];
    float4 p = ((const float4*)hprev)[idx];
    v.x = p.x + fmaxf(fmaf(v.x, sc.x, sh.x), 0.f);
    v.y = p.y + fmaxf(fmaf(v.y, sc.y, sh.y), 0.f);
    v.z = p.z + fmaxf(fmaf(v.z, sc.z, sh.z), 0.f);
    v.w = p.w + fmaxf(fmaf(v.w, sc.w, sh.w), 0.f);
    ((float4*)out)[idx] = v;
}

// ---------------------------------------------------------------------------
// Host launcher
// ---------------------------------------------------------------------------
extern "C" void kernel_launch(void* const* d_in, const int* in_sizes, int n_in,
                              void* d_out, int out_size)
{
    const float* x    = (const float*)d_in[0];
    const int* ei     = (const int*)d_in[1];     // int32 (JAX x64 disabled)
    const float* ew   = (const float*)d_in[2];
    const float* eps1 = (const float*)d_in[3];
    const float* W1a  = (const float*)d_in[4];
    const float* b1a  = (const float*)d_in[5];
    const float* W1b  = (const float*)d_in[6];
    const float* b1b  = (const float*)d_in[7];
    const float* g1   = (const float*)d_in[8];
    const float* be1  = (const float*)d_in[9];
    const float* epss = (const float*)d_in[10];
    const float* Wsa  = (const float*)d_in[11];
    const float* bsa  = (const float*)d_in[12];
    const float* Wsb  = (const float*)d_in[13];
    const float* bsb  = (const float*)d_in[14];
    const float* gs   = (const float*)d_in[15];
    const float* bes  = (const float*)d_in[16];

    const int F   = in_sizes[4] / in_sizes[5];   // 128
    const int N   = in_sizes[0] / F;
    const int E   = in_sizes[2];
    const int Lm1 = in_sizes[10];

    const int* src = ei;
    const int* dst = ei + E;

    float *yb, *zb, *h2b, *hb;
    cudaGetSymbolAddress((void**)&yb,  g_y);
    cudaGetSymbolAddress((void**)&zb,  g_z);
    cudaGetSymbolAddress((void**)&h2b, g_h2);
    cudaGetSymbolAddress((void**)&hb,  g_h);

    const int gemm_blocks = (N + 127) / 128;
    const int scat_blocks = (E + 63) / 64;
    const int bn_blocks   = (N * 16 + 255) / 256;
    const float invN = 1.0f / (float)N;

    // -------- Layer 0 (K = F = 128): GEMM-first (A@W commutes w/ aggregation)
    gemm_a_kernel<128, false><<<gemm_blocks, 256>>>(
        x, W1a, eps1, 0, nullptr, nullptr, 0, 0, invN, /*zero_stats=*/1,
        nullptr, yb, zb, N);
    scatter_kernel<<<scat_blocks, 256>>>(src, dst, ew, yb, zb, E);
    gemm_b_kernel<<<gemm_blocks, 256>>>(zb, W1b, b1a, b1b, h2b, N, /*set*/0);

    // -------- Hidden layers i = 0..Lm1-1: BN of previous layer fused into A-load
    for (int i = 0; i < Lm1; i++) {
        const float* gam = (i == 0) ? g1  : gs  + (size_t)(i - 1) * HDIM;
        const float* bet = (i == 0) ? be1 : bes + (size_t)(i - 1) * HDIM;
        gemm_a_kernel<64, true><<<gemm_blocks, 256>>>(
            h2b, Wsa + (size_t)i * HDIM * HDIM, epss, i,
            gam, bet, /*stat_set=*/i, /*residual=*/(i > 0), invN, 0,
            hb, yb, zb, N);
        scatter_kernel<<<scat_blocks, 256>>>(src, dst, ew, yb, zb, E);
        gemm_b_kernel<<<gemm_blocks, 256>>>(
            zb, Wsb + (size_t)i * HDIM * HDIM,
            bsa + (size_t)i * HDIM, bsb + (size_t)i * HDIM,
            h2b, N, /*set*/i + 1);
    }

    // -------- Final BN + residual into d_out
    bn_apply_final_kernel<<<bn_blocks, 256>>>(
        h2b, hb, (float*)d_out,
        gs + (size_t)(Lm1 - 1) * HDIM, bes + (size_t)(Lm1 - 1) * HDIM,
        /*stat_set=*/Lm1, invN, N);
}